// round 15
// baseline (speedup 1.0000x reference)
#include <cuda_runtime.h>
#include <cuda_bf16.h>
#include <cstdint>

#define EPSV 1e-5f

constexpr int Bsz = 16, D = 384, L = 1024, S = 64, C3 = 192, E = 8, HID = 768;
constexpr int NTOK = Bsz * L;                    // 16384
constexpr int MAXSLOTS = 2 * NTOK + E * 128;     // 33792 (expert-padded)

// ------------------------- scratch (static device globals) -------------------------
__device__ float g_x1[Bsz * D * L];
__device__ float g_mu[NTOK];
__device__ float g_rs[NTOK];
__device__ float g_bcdt[Bsz * C3 * L];
__device__ float g_bcdt2[Bsz * C3 * L];          // only Cm band used
__device__ float g_ab[Bsz * S * L];
__device__ float g_h[Bsz * D * S];
__device__ float g_x2[Bsz * D * L];
__device__ __nv_bfloat16 g_xTb[NTOK * D];
__device__ __nv_bfloat16 g_heb[(size_t)MAXSLOTS * HID];
__device__ __nv_bfloat16 g_w1b[E * HID * D];
__device__ __nv_bfloat16 g_w3b[E * HID * D];
__device__ __nv_bfloat16 g_w2b[E * D * HID];
__device__ int   g_cnt[E];
__device__ int   g_cnt2[E];
__device__ int   g_topk_idx[NTOK * 2];
__device__ float g_topk_w[NTOK * 2];
__device__ int   g_perm[MAXSLOTS];
__device__ float g_wgt[MAXSLOTS];

// ------------------------- mma / async helpers --------------------------------------
__device__ __forceinline__ uint32_t f2tf32(float x) {
    uint32_t r;
    asm("cvt.rna.tf32.f32 %0, %1;" : "=r"(r) : "f"(x));
    return r;
}
__device__ __forceinline__ void mma_tf32(float c[4], uint32_t a0, uint32_t a1,
                                         uint32_t a2, uint32_t a3,
                                         uint32_t b0, uint32_t b1) {
    asm volatile(
        "mma.sync.aligned.m16n8k8.row.col.f32.tf32.tf32.f32 "
        "{%0,%1,%2,%3}, {%4,%5,%6,%7}, {%8,%9}, {%0,%1,%2,%3};"
        : "+f"(c[0]), "+f"(c[1]), "+f"(c[2]), "+f"(c[3])
        : "r"(a0), "r"(a1), "r"(a2), "r"(a3), "r"(b0), "r"(b1));
}
__device__ __forceinline__ void ldm_x4(uint32_t* r, uint32_t addr) {
    asm volatile("ldmatrix.sync.aligned.m8n8.x4.shared.b16 {%0,%1,%2,%3}, [%4];"
                 : "=r"(r[0]), "=r"(r[1]), "=r"(r[2]), "=r"(r[3]) : "r"(addr));
}
__device__ __forceinline__ void mma_bf16(float c[4], const uint32_t a[4],
                                         uint32_t b0, uint32_t b1) {
    asm volatile(
        "mma.sync.aligned.m16n8k16.row.col.f32.bf16.bf16.f32 "
        "{%0,%1,%2,%3}, {%4,%5,%6,%7}, {%8,%9}, {%0,%1,%2,%3};"
        : "+f"(c[0]), "+f"(c[1]), "+f"(c[2]), "+f"(c[3])
        : "r"(a[0]), "r"(a[1]), "r"(a[2]), "r"(a[3]), "r"(b0), "r"(b1));
}
__device__ __forceinline__ void cpa16(uint32_t dst, const void* src) {
    asm volatile("cp.async.cg.shared.global [%0], [%1], 16;" :: "r"(dst), "l"(src));
}
__device__ __forceinline__ void cp_commit() {
    asm volatile("cp.async.commit_group;");
}
__device__ __forceinline__ void cp_wait1() {
    asm volatile("cp.async.wait_group 1;");
}
__device__ __forceinline__ int expert_base(int e) {
    int off = 0;
    for (int q = 0; q < e; q++) off += (g_cnt[q] + 127) & ~127;
    return off;
}

// ---------------- prep: init counters/pads + fp32->bf16 weight convert ---------------
__global__ void k_prep(const float* __restrict__ w1, const float* __restrict__ w3,
                       const float* __restrict__ w2) {
    int t = blockIdx.x * 256 + threadIdx.x;
    if (t < MAXSLOTS) { g_wgt[t] = 0.f; g_perm[t] = 0; }
    if (t < E) { g_cnt[t] = 0; g_cnt2[t] = 0; }
    if (t < Bsz * D * S) g_h[t] = 0.f;
    int i = t * 4;
    constexpr int WN = E * HID * D;
    if (i < WN) {
        float4 v1 = *(const float4*)(w1 + i);
        float4 v3 = *(const float4*)(w3 + i);
        float4 v2 = *(const float4*)(w2 + i);
        *(__nv_bfloat162*)(g_w1b + i)     = __float22bfloat162_rn(make_float2(v1.x, v1.y));
        *(__nv_bfloat162*)(g_w1b + i + 2) = __float22bfloat162_rn(make_float2(v1.z, v1.w));
        *(__nv_bfloat162*)(g_w3b + i)     = __float22bfloat162_rn(make_float2(v3.x, v3.y));
        *(__nv_bfloat162*)(g_w3b + i + 2) = __float22bfloat162_rn(make_float2(v3.z, v3.w));
        *(__nv_bfloat162*)(g_w2b + i)     = __float22bfloat162_rn(make_float2(v2.x, v2.y));
        *(__nv_bfloat162*)(g_w2b + i + 2) = __float22bfloat162_rn(make_float2(v2.z, v2.w));
    }
}

// ------------------------- depthwise 3x3 (+optional BN, +optional residual) ----------
__global__ void k_dwconv(const float* __restrict__ in, const float* __restrict__ w9,
                         const float* __restrict__ g, const float* __restrict__ bb,
                         const float* __restrict__ m, const float* __restrict__ v,
                         float* __restrict__ out, int C, int residual) {
    __shared__ float s[34 * 34];
    int b = blockIdx.x / C, c = blockIdx.x % C;
    const float* ip = in + (size_t)(b * C + c) * L;
    int tid = threadIdx.x;
    for (int idx = tid; idx < 34 * 34; idx += 256) {
        int r = idx / 34 - 1, cc = idx % 34 - 1;
        s[idx] = (r >= 0 && r < 32 && cc >= 0 && cc < 32) ? ip[r * 32 + cc] : 0.f;
    }
    __syncthreads();
    float w[9];
#pragma unroll
    for (int i = 0; i < 9; i++) w[i] = w9[c * 9 + i];
    float sc = 1.f, sh = 0.f;
    if (g) { sc = g[c] * rsqrtf(v[c] + EPSV); sh = bb[c] - m[c] * sc; }
    float* op = out + (size_t)(b * C + c) * L;
    for (int idx = tid; idx < 1024; idx += 256) {
        int r = idx >> 5, cc = idx & 31;
        float acc = 0.f;
#pragma unroll
        for (int kr = 0; kr < 3; kr++)
#pragma unroll
            for (int kc = 0; kc < 3; kc++)
                acc += w[kr * 3 + kc] * s[(r + kr) * 34 + cc + kc];
        float val = sc * acc + sh;
        if (residual) val += s[(r + 1) * 34 + cc + 1];
        op[idx] = val;
    }
}

// ------------------------- LN stats only (mu, rsqrt(var)) ---------------------------
__global__ void k_lnstats() {
    int gi = blockIdx.x * 256 + threadIdx.x;
    int b = gi >> 10, l = gi & 1023;
    const float* p = g_x1 + (size_t)b * D * L + l;
    float sum = 0.f, sq = 0.f;
    for (int d = 0; d < D; d++) { float x = p[(size_t)d * L]; sum += x; sq += x * x; }
    float mu = sum * (1.f / D);
    float var = sq * (1.f / D) - mu * mu;
    g_mu[gi] = mu;
    g_rs[gi] = rsqrtf(var + EPSV);
}

// --------- bcdt = bcdt_w @ LN(x1)  (tf32 mma, LN fused, conflict-free Bs) ------------
__global__ __launch_bounds__(256) void k_gemm_bcdt(const float* __restrict__ Wm,
                                                   const float* __restrict__ lnw,
                                                   const float* __restrict__ lnb) {
    __shared__ uint32_t As[64][20];
    __shared__ uint32_t Bs[16][136];
    int b = blockIdx.x, m0 = blockIdx.y * 64, n0 = blockIdx.z * 128;
    int tid = threadIdx.x, lane = tid & 31, wid = tid >> 5;
    int wm = (wid & 1) * 32, wn = (wid >> 1) * 32;
    int g = lane >> 2, tg = lane & 3;
    const float* Bp = g_x1 + (size_t)b * D * L;

    int mA = tid >> 2, kqA = tid & 3;
    int nB = (tid & 31) * 4, kB = tid >> 5;

    float4 mu4 = *(const float4*)&g_mu[b * L + n0 + nB];
    float4 rs4 = *(const float4*)&g_rs[b * L + n0 + nB];

    float acc[2][4][4] = {};
    float4 ra, rb0, rb1;
    ra  = *(const float4*)&Wm[(size_t)(m0 + mA) * 384 + kqA * 4];
    rb0 = *(const float4*)&Bp[(size_t)kB * L + n0 + nB];
    rb1 = *(const float4*)&Bp[(size_t)(kB + 8) * L + n0 + nB];

    for (int it = 0; it < 24; it++) {
        int d0 = it * 16 + kB;
        float w0 = lnw[d0],     c0 = lnb[d0];
        float w1 = lnw[d0 + 8], c1 = lnb[d0 + 8];
        *(uint4*)&As[mA][kqA * 4] =
            make_uint4(f2tf32(ra.x), f2tf32(ra.y), f2tf32(ra.z), f2tf32(ra.w));
        *(uint4*)&Bs[kB][nB] = make_uint4(
            f2tf32((rb0.x - mu4.x) * rs4.x * w0 + c0),
            f2tf32((rb0.y - mu4.y) * rs4.y * w0 + c0),
            f2tf32((rb0.z - mu4.z) * rs4.z * w0 + c0),
            f2tf32((rb0.w - mu4.w) * rs4.w * w0 + c0));
        *(uint4*)&Bs[kB + 8][nB] = make_uint4(
            f2tf32((rb1.x - mu4.x) * rs4.x * w1 + c1),
            f2tf32((rb1.y - mu4.y) * rs4.y * w1 + c1),
            f2tf32((rb1.z - mu4.z) * rs4.z * w1 + c1),
            f2tf32((rb1.w - mu4.w) * rs4.w * w1 + c1));
        __syncthreads();
        if (it + 1 < 24) {
            int k0 = (it + 1) * 16;
            ra  = *(const float4*)&Wm[(size_t)(m0 + mA) * 384 + k0 + kqA * 4];
            rb0 = *(const float4*)&Bp[(size_t)(k0 + kB) * L + n0 + nB];
            rb1 = *(const float4*)&Bp[(size_t)(k0 + kB + 8) * L + n0 + nB];
        }
#pragma unroll
        for (int ks = 0; ks < 16; ks += 8) {
            uint32_t af[2][4], bf[4][2];
#pragma unroll
            for (int mt = 0; mt < 2; mt++) {
                int r = wm + mt * 16 + g;
                af[mt][0] = As[r][ks + tg];     af[mt][1] = As[r + 8][ks + tg];
                af[mt][2] = As[r][ks + 4 + tg]; af[mt][3] = As[r + 8][ks + 4 + tg];
            }
#pragma unroll
            for (int nt = 0; nt < 4; nt++) {
                int c = wn + nt * 8 + g;
                bf[nt][0] = Bs[ks + tg][c]; bf[nt][1] = Bs[ks + 4 + tg][c];
            }
#pragma unroll
            for (int mt = 0; mt < 2; mt++)
#pragma unroll
                for (int nt = 0; nt < 4; nt++)
                    mma_tf32(acc[mt][nt], af[mt][0], af[mt][1], af[mt][2], af[mt][3],
                             bf[nt][0], bf[nt][1]);
        }
        __syncthreads();
    }
    float* Cp = g_bcdt + (size_t)b * C3 * L;
#pragma unroll
    for (int mt = 0; mt < 2; mt++)
#pragma unroll
        for (int h = 0; h < 2; h++) {
            int row = m0 + wm + mt * 16 + g + h * 8;
#pragma unroll
            for (int nt = 0; nt < 4; nt++) {
                int col = n0 + wn + nt * 8 + tg * 2;
                Cp[(size_t)row * L + col]     = acc[mt][nt][h * 2];
                Cp[(size_t)row * L + col + 1] = acc[mt][nt][h * 2 + 1];
            }
        }
}

// ------- fused dws-conv (Bm, Cm, dt) + softmax over L + ab = softmax(dt)*Bm ----------
__global__ __launch_bounds__(256) void k_dwsmax(const float* __restrict__ dws_w) {
    __shared__ float sB[34 * 34], sC[34 * 34], sD[34 * 34];
    __shared__ float red[256];
    int b = blockIdx.x, s = blockIdx.y;
    int tid = threadIdx.x;
    const float* ipB = g_bcdt + ((size_t)b * C3 + s) * L;
    const float* ipC = g_bcdt + ((size_t)b * C3 + S + s) * L;
    const float* ipD = g_bcdt + ((size_t)b * C3 + 2 * S + s) * L;
    for (int idx = tid; idx < 34 * 34; idx += 256) {
        int r = idx / 34 - 1, cc = idx % 34 - 1;
        bool in = (r >= 0 && r < 32 && cc >= 0 && cc < 32);
        int o = r * 32 + cc;
        sB[idx] = in ? ipB[o] : 0.f;
        sC[idx] = in ? ipC[o] : 0.f;
        sD[idx] = in ? ipD[o] : 0.f;
    }
    __syncthreads();
    float wB[9], wC[9], wD[9];
#pragma unroll
    for (int i = 0; i < 9; i++) {
        wB[i] = dws_w[s * 9 + i];
        wC[i] = dws_w[(S + s) * 9 + i];
        wD[i] = dws_w[(2 * S + s) * 9 + i];
    }
    float bm[4], dt[4];
    float* Cp = g_bcdt2 + ((size_t)b * C3 + S + s) * L;
    float mx = -1e30f;
#pragma unroll
    for (int i = 0; i < 4; i++) {
        int idx = tid + i * 256;
        int r = idx >> 5, cc = idx & 31;
        float aB = 0.f, aC = 0.f, aD = 0.f;
#pragma unroll
        for (int kr = 0; kr < 3; kr++)
#pragma unroll
            for (int kc = 0; kc < 3; kc++) {
                float vB = sB[(r + kr) * 34 + cc + kc];
                float vC = sC[(r + kr) * 34 + cc + kc];
                float vD = sD[(r + kr) * 34 + cc + kc];
                aB += wB[kr * 3 + kc] * vB;
                aC += wC[kr * 3 + kc] * vC;
                aD += wD[kr * 3 + kc] * vD;
            }
        bm[i] = aB; dt[i] = aD;
        Cp[idx] = aC;
        mx = fmaxf(mx, aD);
    }
    red[tid] = mx; __syncthreads();
    for (int o = 128; o > 0; o >>= 1) { if (tid < o) red[tid] = fmaxf(red[tid], red[tid + o]); __syncthreads(); }
    mx = red[0]; __syncthreads();
    float e[4]; float sum = 0.f;
#pragma unroll
    for (int i = 0; i < 4; i++) { e[i] = __expf(dt[i] - mx); sum += e[i]; }
    red[tid] = sum; __syncthreads();
    for (int o = 128; o > 0; o >>= 1) { if (tid < o) red[tid] += red[tid + o]; __syncthreads(); }
    float inv = 1.f / red[0];
    float* ab = g_ab + ((size_t)b * S + s) * L;
#pragma unroll
    for (int i = 0; i < 4; i++) ab[tid + i * 256] = e[i] * inv * bm[i];
}

// --- h[b,d,s] = sum_l LN(x1)*ab  (tf32 mma, LN fused, conflict-free Bs, split-K=4) ---
__global__ __launch_bounds__(256) void k_gemm_h(const float* __restrict__ lnw,
                                                const float* __restrict__ lnb) {
    __shared__ uint32_t As[128][20];
    __shared__ uint32_t Bs[64][20];
    __shared__ float smu[256], srs[256];
    int b = blockIdx.x, m0 = blockIdx.y * 128, kc = blockIdx.z;
    int tid = threadIdx.x, lane = tid & 31, wid = tid >> 5;
    int wm = (wid & 3) * 32, wn = (wid >> 2) * 32;
    int g = lane >> 2, tg = lane & 3;
    const float* Ap = g_x1 + (size_t)b * D * L;
    const float* Bp = g_ab + (size_t)b * S * L;

    int mA = tid >> 1, lhA = tid & 1;
    int nB = tid >> 2, kqB = tid & 3;
    int kbase = kc * 256;

    smu[tid] = g_mu[b * L + kbase + tid];
    srs[tid] = g_rs[b * L + kbase + tid];
    float wA = lnw[m0 + mA], cA = lnb[m0 + mA];
    __syncthreads();

    float acc[2][4][4] = {};
    float4 ra0, ra1, rb;
    ra0 = *(const float4*)&Ap[(size_t)(m0 + mA) * L + kbase + lhA * 8];
    ra1 = *(const float4*)&Ap[(size_t)(m0 + mA) * L + kbase + lhA * 8 + 4];
    rb  = *(const float4*)&Bp[(size_t)nB * L + kbase + kqB * 4];

    for (int it = 0; it < 16; it++) {
        int lx = it * 16 + lhA * 8;
        *(uint4*)&As[mA][lhA * 8] = make_uint4(
            f2tf32((ra0.x - smu[lx + 0]) * srs[lx + 0] * wA + cA),
            f2tf32((ra0.y - smu[lx + 1]) * srs[lx + 1] * wA + cA),
            f2tf32((ra0.z - smu[lx + 2]) * srs[lx + 2] * wA + cA),
            f2tf32((ra0.w - smu[lx + 3]) * srs[lx + 3] * wA + cA));
        *(uint4*)&As[mA][lhA * 8 + 4] = make_uint4(
            f2tf32((ra1.x - smu[lx + 4]) * srs[lx + 4] * wA + cA),
            f2tf32((ra1.y - smu[lx + 5]) * srs[lx + 5] * wA + cA),
            f2tf32((ra1.z - smu[lx + 6]) * srs[lx + 6] * wA + cA),
            f2tf32((ra1.w - smu[lx + 7]) * srs[lx + 7] * wA + cA));
        Bs[nB][kqB * 4 + 0] = f2tf32(rb.x); Bs[nB][kqB * 4 + 1] = f2tf32(rb.y);
        Bs[nB][kqB * 4 + 2] = f2tf32(rb.z); Bs[nB][kqB * 4 + 3] = f2tf32(rb.w);
        __syncthreads();
        if (it + 1 < 16) {
            int k0 = kbase + (it + 1) * 16;
            ra0 = *(const float4*)&Ap[(size_t)(m0 + mA) * L + k0 + lhA * 8];
            ra1 = *(const float4*)&Ap[(size_t)(m0 + mA) * L + k0 + lhA * 8 + 4];
            rb  = *(const float4*)&Bp[(size_t)nB * L + k0 + kqB * 4];
        }
#pragma unroll
        for (int ks = 0; ks < 16; ks += 8) {
            uint32_t af[2][4], bf[4][2];
#pragma unroll
            for (int mt = 0; mt < 2; mt++) {
                int r = wm + mt * 16 + g;
                af[mt][0] = As[r][ks + tg];     af[mt][1] = As[r + 8][ks + tg];
                af[mt][2] = As[r][ks + 4 + tg]; af[mt][3] = As[r + 8][ks + 4 + tg];
            }
#pragma unroll
            for (int nt = 0; nt < 4; nt++) {
                int c = wn + nt * 8 + g;
                bf[nt][0] = Bs[c][ks + tg]; bf[nt][1] = Bs[c][ks + 4 + tg];
            }
#pragma unroll
            for (int mt = 0; mt < 2; mt++)
#pragma unroll
                for (int nt = 0; nt < 4; nt++)
                    mma_tf32(acc[mt][nt], af[mt][0], af[mt][1], af[mt][2], af[mt][3],
                             bf[nt][0], bf[nt][1]);
        }
        __syncthreads();
    }
    float* Cp = g_h + (size_t)b * D * S;
#pragma unroll
    for (int mt = 0; mt < 2; mt++)
#pragma unroll
        for (int h = 0; h < 2; h++) {
            int row = m0 + wm + mt * 16 + g + h * 8;
#pragma unroll
            for (int nt = 0; nt < 4; nt++) {
                int col = wn + nt * 8 + tg * 2;
                atomicAdd(&Cp[(size_t)row * S + col],     acc[mt][nt][h * 2]);
                atomicAdd(&Cp[(size_t)row * S + col + 1], acc[mt][nt][h * 2 + 1]);
            }
        }
}

// ------------- h2 = silu(hproj @ h) -> out_h  (tf32 mma, 128x64 tiles, K=384) --------
__global__ __launch_bounds__(256) void k_hproj(const float* __restrict__ Wp,
                                               float* __restrict__ outh) {
    __shared__ uint32_t As[128][20];
    __shared__ uint32_t Bs[64][20];
    int b = blockIdx.x, m0 = blockIdx.y * 128;
    int tid = threadIdx.x, lane = tid & 31, wid = tid >> 5;
    int wm = (wid & 3) * 32, wn = (wid >> 2) * 32;
    int g = lane >> 2, tg = lane & 3;
    const float* Bp = g_h + (size_t)b * D * S;

    int mA = tid >> 1, lhA = tid & 1;
    int nB = tid & 63, kqB = tid >> 6;

    float acc[2][4][4] = {};
    float4 ra0, ra1;
    float rb[4];
    ra0 = *(const float4*)&Wp[(size_t)(m0 + mA) * 384 + lhA * 8];
    ra1 = *(const float4*)&Wp[(size_t)(m0 + mA) * 384 + lhA * 8 + 4];
#pragma unroll
    for (int j = 0; j < 4; j++) rb[j] = Bp[(size_t)(kqB * 4 + j) * S + nB];

    for (int it = 0; it < 24; it++) {
        *(uint4*)&As[mA][lhA * 8] =
            make_uint4(f2tf32(ra0.x), f2tf32(ra0.y), f2tf32(ra0.z), f2tf32(ra0.w));
        *(uint4*)&As[mA][lhA * 8 + 4] =
            make_uint4(f2tf32(ra1.x), f2tf32(ra1.y), f2tf32(ra1.z), f2tf32(ra1.w));
#pragma unroll
        for (int j = 0; j < 4; j++) Bs[nB][kqB * 4 + j] = f2tf32(rb[j]);
        __syncthreads();
        if (it + 1 < 24) {
            int k0 = (it + 1) * 16;
            ra0 = *(const float4*)&Wp[(size_t)(m0 + mA) * 384 + k0 + lhA * 8];
            ra1 = *(const float4*)&Wp[(size_t)(m0 + mA) * 384 + k0 + lhA * 8 + 4];
#pragma unroll
            for (int j = 0; j < 4; j++) rb[j] = Bp[(size_t)(k0 + kqB * 4 + j) * S + nB];
        }
#pragma unroll
        for (int ks = 0; ks < 16; ks += 8) {
            uint32_t af[2][4], bf[4][2];
#pragma unroll
            for (int mt = 0; mt < 2; mt++) {
                int r = wm + mt * 16 + g;
                af[mt][0] = As[r][ks + tg];     af[mt][1] = As[r + 8][ks + tg];
                af[mt][2] = As[r][ks + 4 + tg]; af[mt][3] = As[r + 8][ks + 4 + tg];
            }
#pragma unroll
            for (int nt = 0; nt < 4; nt++) {
                int c = wn + nt * 8 + g;
                bf[nt][0] = Bs[c][ks + tg]; bf[nt][1] = Bs[c][ks + 4 + tg];
            }
#pragma unroll
            for (int mt = 0; mt < 2; mt++)
#pragma unroll
                for (int nt = 0; nt < 4; nt++)
                    mma_tf32(acc[mt][nt], af[mt][0], af[mt][1], af[mt][2], af[mt][3],
                             bf[nt][0], bf[nt][1]);
        }
        __syncthreads();
    }
    float* Cp = outh + (size_t)b * D * S;
#pragma unroll
    for (int mt = 0; mt < 2; mt++)
#pragma unroll
        for (int h = 0; h < 2; h++) {
            int row = m0 + wm + mt * 16 + g + h * 8;
#pragma unroll
            for (int nt = 0; nt < 4; nt++) {
                int col = wn + nt * 8 + tg * 2;
                float xa = acc[mt][nt][h * 2];
                float xb = acc[mt][nt][h * 2 + 1];
                Cp[(size_t)row * S + col]     = xa / (1.f + __expf(-xa));
                Cp[(size_t)row * S + col + 1] = xb / (1.f + __expf(-xb));
            }
        }
}

// ------------- x2 = x1 + h2 @ Cm  (tf32 mma, conflict-free Bs, K=64) -----------------
__global__ __launch_bounds__(256) void k_gemm_y(const float* __restrict__ outh) {
    __shared__ uint32_t As[128][20];
    __shared__ uint32_t Bs[16][136];
    int b = blockIdx.x, m0 = blockIdx.y * 128, n0 = blockIdx.z * 128;
    int tid = threadIdx.x, lane = tid & 31, wid = tid >> 5;
    int wm = (wid & 1) * 64, wn = (wid >> 1) * 32;
    int g = lane >> 2, tg = lane & 3;
    const float* Ap = outh + (size_t)b * D * S;
    const float* Bp = g_bcdt2 + ((size_t)b * C3 + S) * L;

    int mA = tid >> 1, lhA = tid & 1;
    int nB = (tid & 31) * 4, kB = tid >> 5;

    float acc[4][4][4] = {};
    float4 ra0, ra1, rb0, rb1;
    ra0 = *(const float4*)&Ap[(size_t)(m0 + mA) * S + lhA * 8];
    ra1 = *(const float4*)&Ap[(size_t)(m0 + mA) * S + lhA * 8 + 4];
    rb0 = *(const float4*)&Bp[(size_t)kB * L + n0 + nB];
    rb1 = *(const float4*)&Bp[(size_t)(kB + 8) * L + n0 + nB];

    for (int it = 0; it < 4; it++) {
        *(uint4*)&As[mA][lhA * 8] =
            make_uint4(f2tf32(ra0.x), f2tf32(ra0.y), f2tf32(ra0.z), f2tf32(ra0.w));
        *(uint4*)&As[mA][lhA * 8 + 4] =
            make_uint4(f2tf32(ra1.x), f2tf32(ra1.y), f2tf32(ra1.z), f2tf32(ra1.w));
        *(uint4*)&Bs[kB][nB] =
            make_uint4(f2tf32(rb0.x), f2tf32(rb0.y), f2tf32(rb0.z), f2tf32(rb0.w));
        *(uint4*)&Bs[kB + 8][nB] =
            make_uint4(f2tf32(rb1.x), f2tf32(rb1.y), f2tf32(rb1.z), f2tf32(rb1.w));
        __syncthreads();
        if (it + 1 < 4) {
            int k0 = (it + 1) * 16;
            ra0 = *(const float4*)&Ap[(size_t)(m0 + mA) * S + k0 + lhA * 8];
            ra1 = *(const float4*)&Ap[(size_t)(m0 + mA) * S + k0 + lhA * 8 + 4];
            rb0 = *(const float4*)&Bp[(size_t)(k0 + kB) * L + n0 + nB];
            rb1 = *(const float4*)&Bp[(size_t)(k0 + kB + 8) * L + n0 + nB];
        }
#pragma unroll
        for (int ks = 0; ks < 16; ks += 8) {
            uint32_t af[4][4], bf[4][2];
#pragma unroll
            for (int mt = 0; mt < 4; mt++) {
                int r = wm + mt * 16 + g;
                af[mt][0] = As[r][ks + tg];     af[mt][1] = As[r + 8][ks + tg];
                af[mt][2] = As[r][ks + 4 + tg]; af[mt][3] = As[r + 8][ks + 4 + tg];
            }
#pragma unroll
            for (int nt = 0; nt < 4; nt++) {
                int c = wn + nt * 8 + g;
                bf[nt][0] = Bs[ks + tg][c]; bf[nt][1] = Bs[ks + 4 + tg][c];
            }
#pragma unroll
            for (int mt = 0; mt < 4; mt++)
#pragma unroll
                for (int nt = 0; nt < 4; nt++)
                    mma_tf32(acc[mt][nt], af[mt][0], af[mt][1], af[mt][2], af[mt][3],
                             bf[nt][0], bf[nt][1]);
        }
        __syncthreads();
    }
#pragma unroll
    for (int mt = 0; mt < 4; mt++)
#pragma unroll
        for (int h = 0; h < 2; h++) {
            int row = m0 + wm + mt * 16 + g + h * 8;
#pragma unroll
            for (int nt = 0; nt < 4; nt++) {
                int col = n0 + wn + nt * 8 + tg * 2;
                size_t o = (size_t)b * D * L + (size_t)row * L + col;
                g_x2[o]     = g_x1[o]     + acc[mt][nt][h * 2];
                g_x2[o + 1] = g_x1[o + 1] + acc[mt][nt][h * 2 + 1];
            }
        }
}

// ---------- fused: NCHW -> bf16 token transpose + router (logits in fp32) ------------
__global__ __launch_bounds__(256) void k_transroute(
        const float* __restrict__ xin, const float* __restrict__ gw,
        const float* __restrict__ gb) {
    __shared__ float sg[E * 385];
    __shared__ float s[32][33];
    __shared__ float lgb[32][8];
    int b = blockIdx.x, l0 = blockIdx.y * 32;
    int tid = threadIdx.x;
    for (int i = tid; i < E * D; i += 256)
        sg[(i / D) * 385 + (i % D)] = gw[i];

    int rr = tid >> 5, cc = tid & 31;
    int ch = tid & 31, tk = tid >> 5;
    int tok = tid >> 3, ex = tid & 7;
    float lg = 0.f;

    for (int dc = 0; dc < 12; dc++) {
        int d0 = dc * 32;
        __syncthreads();
#pragma unroll
        for (int i = 0; i < 4; i++)
            s[rr + i * 8][cc] = xin[((size_t)b * D + d0 + rr + i * 8) * L + l0 + cc];
        __syncthreads();
#pragma unroll
        for (int j = 0; j < 4; j++) {
            int t2 = tk + j * 8;
            g_xTb[((size_t)b * L + l0 + t2) * D + d0 + ch] =
                __float2bfloat16(s[ch][t2]);
        }
        const float* gp = sg + ex * 385 + d0;
#pragma unroll
        for (int dd = 0; dd < 32; dd++)
            lg += s[dd][tok] * gp[dd];
    }
    lgb[tok][ex] = lg;
    __syncthreads();
    if (tid < 32) {
        int n = b * L + l0 + tid;
        float v[E];
#pragma unroll
        for (int e = 0; e < E; e++) v[e] = lgb[tid][e] + gb[e];
        int i0 = 0; float v0 = v[0];
#pragma unroll
        for (int e = 1; e < E; e++) if (v[e] > v0) { v0 = v[e]; i0 = e; }
        int i1 = -1; float v1 = -1e30f;
#pragma unroll
        for (int e = 0; e < E; e++) if (e != i0 && v[e] > v1) { v1 = v[e]; i1 = e; }
        float p0 = 1.f / (1.f + __expf(v1 - v0));
        g_topk_idx[n * 2] = i0; g_topk_idx[n * 2 + 1] = i1;
        g_topk_w[n * 2] = p0;   g_topk_w[n * 2 + 1] = 1.f - p0;
        atomicAdd(&g_cnt[i0], 1); atomicAdd(&g_cnt[i1], 1);
    }
}

// ---------------- scatter (offsets computed inline from g_cnt) -----------------------
__global__ void k_scatter() {
    __shared__ int soff[E];
    if (threadIdx.x < E) soff[threadIdx.x] = expert_base(threadIdx.x);
    __syncthreads();
    int n = blockIdx.x * 256 + threadIdx.x;
#pragma unroll
    for (int k = 0; k < 2; k++) {
        int e = g_topk_idx[n * 2 + k];
        int pos = soff[e] + atomicAdd(&g_cnt2[e], 1);
        g_perm[pos] = n;
        g_wgt[pos] = g_topk_w[n * 2 + k];
    }
}

// ------------------- MoE GEMM1 (bf16 mma + cp.async 3-stage, k-tile 64) --------------
// Grid: (mtile, expert, ntile) -> consecutive CTAs share the same weight tile in L2.
constexpr int MT_BYTES = 18432;       // 128 rows * 144B
constexpr int MOE1_SMEM = 166400;
constexpr int MOE2_SMEM = 110592;

__global__ __launch_bounds__(256) void k_moe1(
        const float* __restrict__ B1, const float* __restrict__ B3) {
    extern __shared__ char sm[];
    int* sperm = (int*)(sm + 165888);

    int e = blockIdx.y;
    int cnt = g_cnt[e];
    int m0 = blockIdx.x * 128;
    if (m0 >= cnt) return;
    int base = expert_base(e);
    int n0 = blockIdx.z * 128;

    int tid = threadIdx.x, lane = tid & 31, wid = tid >> 5;
    int wm = (wid & 1) * 64, wn = (wid >> 1) * 32;
    int g = lane >> 2, tg = lane & 3;

    if (tid < 128) sperm[tid] = g_perm[base + m0 + tid];
    __syncthreads();

    uint32_t smBase = (uint32_t)__cvta_generic_to_shared(sm);
    uint32_t aFrag = (wm + (lane & 15)) * 144 + (lane >> 4) * 16;
    uint32_t bFrag = (wn + (lane >> 4) * 8 + (lane & 7)) * 144 + ((lane >> 3) & 1) * 16;

    constexpr int KT = D / 64;   // 6
    auto issue = [&](int t) {
        if (t < KT) {
            int k0 = t * 64;
            uint32_t off = (uint32_t)(t % 3) * MT_BYTES;
#pragma unroll
            for (int j = 0; j < 4; j++) {
                int li = tid + j * 256;
                int row = li >> 3, lc = li & 7;
                uint32_t so = off + row * 144 + lc * 16;
                cpa16(smBase + so, g_xTb + (size_t)sperm[row] * D + k0 + lc * 8);
                size_t wgo = ((size_t)e * HID + n0 + row) * D + k0 + lc * 8;
                cpa16(smBase + 55296 + so,  g_w1b + wgo);
                cpa16(smBase + 110592 + so, g_w3b + wgo);
            }
        }
        cp_commit();
    };

    float acc1[4][4][4] = {}, acc3[4][4][4] = {};
    issue(0); issue(1);

    for (int it = 0; it < KT; it++) {
        cp_wait1();
        __syncthreads();
        issue(it + 2);
        uint32_t st = (uint32_t)(it % 3) * MT_BYTES;
#pragma unroll
        for (int ks = 0; ks < 4; ks++) {
            uint32_t af[4][4], bf1[2][4], bf3[2][4];
#pragma unroll
            for (int mt = 0; mt < 4; mt++)
                ldm_x4(af[mt], smBase + st + aFrag + mt * 2304 + ks * 32);
#pragma unroll
            for (int np = 0; np < 2; np++) {
                ldm_x4(bf1[np], smBase + 55296 + st + bFrag + np * 2304 + ks * 32);
                ldm_x4(bf3[np], smBase + 110592 + st + bFrag + np * 2304 + ks * 32);
            }
#pragma unroll
            for (int mt = 0; mt < 4; mt++)
#pragma unroll
                for (int nt = 0; nt < 4; nt++) {
                    int np = nt >> 1, hf = (nt & 1) * 2;
                    mma_bf16(acc1[mt][nt], af[mt], bf1[np][hf], bf1[np][hf + 1]);
                    mma_bf16(acc3[mt][nt], af[mt], bf3[np][hf], bf3[np][hf + 1]);
                }
        }
    }

#pragma unroll
    for (int mt = 0; mt < 4; mt++) {
#pragma unroll
        for (int nt = 0; nt < 4; nt++) {
            int cl = n0 + wn + nt * 8 + tg * 2;
            float bb1a = B1[e * HID + cl], bb1b = B1[e * HID + cl + 1];
            float bb3a = B3[e * HID + cl], bb3b = B3[e * HID + cl + 1];
#pragma unroll
            for (int h = 0; h < 2; h++) {
                int rl = wm + mt * 16 + g + h * 8;
                float x1a = acc1[mt][nt][h * 2] + bb1a;
                float x1b = acc1[mt][nt][h * 2 + 1] + bb1b;
                float x3a = acc3[mt][nt][h * 2] + bb3a;
                float x3b = acc3[mt][nt][h * 2 + 1] + bb3b;
                float oa = (x1a / (1.f + __expf(-x1a))) * x3a;
                float ob = (x1b / (1.f + __expf(-x1b))) * x3b;
                *(__nv_bfloat162*)&g_heb[(size_t)(base + m0 + rl) * HID + cl] =
                    __float22bfloat162_rn(make_float2(oa, ob));
            }
        }
    }
}

// ------------------- MoE GEMM2 (bf16 mma + cp.async 3-stage, 2 CTAs/SM) --------------
__global__ __launch_bounds__(256, 2) void k_moe2(
        const float* __restrict__ b2v, float* __restrict__ outx) {
    extern __shared__ char sm[];

    int e = blockIdx.y;
    int cnt = g_cnt[e];
    int m0 = blockIdx.x * 128;
    if (m0 >= cnt) return;
    int base = expert_base(e);
    int n0 = blockIdx.z * 128;

    int tid = threadIdx.x, lane = tid & 31, wid = tid >> 5;
    int wm = (wid & 1) * 64, wn = (wid >> 1) * 32;
    int g = lane >> 2, tg = lane & 3;

    uint32_t smBase = (uint32_t)__cvta_generic_to_shared(sm);
    uint32_t aFrag = (wm + (lane & 15)) * 144 + (lane >> 4) * 16;
    uint32_t bFrag = (wn + (lane >> 4) * 8 + (lane & 7)) * 144 + ((lane >> 3) & 1) * 16;

    constexpr int KT = HID / 64;  // 12
    auto issue = [&](int t) {
        if (t < KT) {
            int k0 = t * 64;
            uint32_t off = (uint32_t)(t % 3) * MT_BYTES;
#pragma unroll
            for (int j = 0; j < 4; j++) {
                int li = tid + j * 256;
                int row = li >> 3, lc = li & 7;
                uint32_t so = off + row * 144 + lc * 16;
                cpa16(smBase + so,
                      g_heb + (size_t)(base + m0 + row) * HID + k0 + lc * 8);
                cpa16(smBase + 55296 + so,
                      g_w2b + ((size_t)e * D + n0 + row) * HID + k0 + lc * 8);
            }
        }
        cp_commit();
    };

    float acc[4][4][4] = {};
    issue(0); issue(1);

    for (int it = 0; it < KT; it++) {
        cp_wait1();
        __syncthreads();
        issue(it + 2);
        uint32_t st = (uint32_t)(it % 3) * MT_BYTES;
#pragma unroll
        for (int ks = 0; ks < 4; ks++) {
            uint32_t af[4][4], bf[2][4];
#pragma unroll
            for (int mt = 0; mt < 4; mt++)
                ldm_x4(af[mt], smBase + st + aFrag + mt * 2304 + ks * 32);
#pragma unroll
            for (int np = 0; np < 2; np++)
                ldm_x4(bf[np], smBase + 55296 + st + bFrag + np * 2304 + ks * 32);
#pragma unroll
            for (int mt = 0; mt < 4; mt++)
#pragma unroll
                for (int nt = 0; nt < 4; nt++) {
                    int np = nt >> 1, hf = (nt & 1) * 2;
                    mma_bf16(acc[mt][nt], af[mt], bf[np][hf], bf[np][hf + 1]);
                }
        }
    }

#pragma unroll
    for (int mt = 0; mt < 4; mt++) {
#pragma unroll
        for (int h = 0; h < 2; h++) {
            int rl = wm + mt * 16 + g + h * 8;
            float w = g_wgt[base + m0 + rl];
            if (w == 0.f) continue;
            int n = g_perm[base + m0 + rl];
            int b = n >> 10, l = n & 1023;
#pragma unroll
            for (int nt = 0; nt < 4; nt++) {
                int cl = n0 + wn + nt * 8 + tg * 2;
                float v0 = (acc[mt][nt][h * 2] + b2v[e * D + cl]) * w;
                float v1 = (acc[mt][nt][h * 2 + 1] + b2v[e * D + cl + 1]) * w;
                atomicAdd(&outx[((size_t)b * D + cl) * L + l], v0);
                atomicAdd(&outx[((size_t)b * D + cl + 1) * L + l], v1);
            }
        }
    }
}

// ------------------------- launch ---------------------------------------------------
extern "C" void kernel_launch(void* const* d_in, const int* in_sizes, int n_in,
                              void* d_out, int out_size) {
    const float* x      = (const float*)d_in[0];
    const float* dw1_w  = (const float*)d_in[1];
    const float* bn1_g  = (const float*)d_in[2];
    const float* bn1_b  = (const float*)d_in[3];
    const float* bn1_m  = (const float*)d_in[4];
    const float* bn1_v  = (const float*)d_in[5];
    const float* dw2_w  = (const float*)d_in[6];
    const float* bn2_g  = (const float*)d_in[7];
    const float* bn2_b  = (const float*)d_in[8];
    const float* bn2_m  = (const float*)d_in[9];
    const float* bn2_v  = (const float*)d_in[10];
    const float* ln_w   = (const float*)d_in[11];
    const float* ln_b   = (const float*)d_in[12];
    const float* bcdt_w = (const float*)d_in[13];
    const float* dws_w  = (const float*)d_in[14];
    const float* hproj_w= (const float*)d_in[15];
    // d_in[16] = A (cancels inside softmax over L)
    const float* gate_w = (const float*)d_in[17];
    const float* gate_b = (const float*)d_in[18];
    const float* w1     = (const float*)d_in[19];
    const float* b1     = (const float*)d_in[20];
    const float* w2     = (const float*)d_in[21];
    const float* b2     = (const float*)d_in[22];
    const float* w3     = (const float*)d_in[23];
    const float* b3     = (const float*)d_in[24];

    float* out_x = (float*)d_out;
    float* out_h = out_x + (size_t)Bsz * D * L;

    float* px1;    cudaGetSymbolAddress((void**)&px1, g_x1);
    float* px2;    cudaGetSymbolAddress((void**)&px2, g_x2);

    static bool init_done = false;
    static cudaStream_t s2 = nullptr;
    static cudaEvent_t evFork = nullptr, evJoin = nullptr;
    if (!init_done) {
        cudaFuncSetAttribute(k_moe1, cudaFuncAttributeMaxDynamicSharedMemorySize, MOE1_SMEM);
        cudaFuncSetAttribute(k_moe2, cudaFuncAttributeMaxDynamicSharedMemorySize, MOE2_SMEM);
        if (cudaStreamCreateWithFlags(&s2, cudaStreamNonBlocking) != cudaSuccess) s2 = nullptr;
        if (s2) {
            if (cudaEventCreateWithFlags(&evFork, cudaEventDisableTiming) != cudaSuccess ||
                cudaEventCreateWithFlags(&evJoin, cudaEventDisableTiming) != cudaSuccess) {
                s2 = nullptr;
            }
        }
        init_done = true;
    }

    // prep (init + weight conversion): forked onto s2 when available
    if (s2) {
        cudaEventRecord(evFork, 0);
        cudaStreamWaitEvent(s2, evFork, 0);
        k_prep<<<2304, 256, 0, s2>>>(w1, w3, w2);
        cudaEventRecord(evJoin, s2);
    } else {
        k_prep<<<2304, 256>>>(w1, w3, w2);
    }

    // x1 = x + bn1(dw1(x))
    k_dwconv<<<Bsz * D, 256>>>(x, dw1_w, bn1_g, bn1_b, bn1_m, bn1_v, px1, D, 1);
    // LN stats only (normalization fused into consumers)
    k_lnstats<<<NTOK / 256, 256>>>();
    // bcdt (tf32, LN fused into B-operand load)
    k_gemm_bcdt<<<dim3(Bsz, 3, 8), 256>>>(bcdt_w, ln_w, ln_b);
    // fused dws conv + softmax (Cm -> g_bcdt2, ab -> g_ab)
    k_dwsmax<<<dim3(Bsz, S), 256>>>(dws_w);
    // join prep before g_h atomics (k_gemm_h needs g_h zeroed)
    if (s2) cudaStreamWaitEvent(0, evJoin, 0);
    // h = LN(x1) @ (Am*Bm)^T (tf32, LN fused into A-operand load, split-K=4)
    k_gemm_h<<<dim3(Bsz, 3, 4), 256>>>(ln_w, ln_b);
    // h2 = silu(hproj @ h) -> second output (tf32 mma)
    k_hproj<<<dim3(Bsz, 3), 256>>>(hproj_w, out_h);
    // x2 = x1 + h2 @ Cm (tf32)
    k_gemm_y<<<dim3(Bsz, 3, 8), 256>>>(out_h);
    // x3 = x2 + bn2(dw2(x2)) -> first output (MoE adds on top)
    k_dwconv<<<Bsz * D, 256>>>(px2, dw2_w, bn2_g, bn2_b, bn2_m, bn2_v, out_x, D, 1);
    // fused bf16 transpose + router
    k_transroute<<<dim3(Bsz, 32), 256>>>(out_x, gate_w, gate_b);
    // scatter (expert offsets computed inline)
    k_scatter<<<NTOK / 256, 256>>>();
    // MoE (bf16 mma.sync; mtile-major grid for weight L2 locality)
    k_moe1<<<dim3(128, E, 6), 256, MOE1_SMEM>>>(b1, b3);
    k_moe2<<<dim3(128, E, 3), 256, MOE2_SMEM>>>(b2, out_x);
}

// round 16
// speedup vs baseline: 1.0205x; 1.0205x over previous
#include <cuda_runtime.h>
#include <cuda_bf16.h>
#include <cstdint>

#define EPSV 1e-5f

constexpr int Bsz = 16, D = 384, L = 1024, S = 64, C3 = 192, E = 8, HID = 768;
constexpr int NTOK = Bsz * L;                    // 16384
constexpr int MAXSLOTS = 2 * NTOK + E * 128;     // 33792 (expert-padded)

// ------------------------- scratch (static device globals) -------------------------
__device__ float g_x1[Bsz * D * L];
__device__ float g_mu[NTOK];
__device__ float g_rs[NTOK];
__device__ float g_bcdt[Bsz * C3 * L];
__device__ float g_bcdt2[Bsz * C3 * L];          // only Cm band used
__device__ float g_ab[Bsz * S * L];
__device__ float g_h[Bsz * D * S];
__device__ float g_x2[Bsz * D * L];
__device__ __nv_bfloat16 g_xTb[NTOK * D];
__device__ __nv_bfloat16 g_heb[(size_t)MAXSLOTS * HID];
__device__ __nv_bfloat16 g_w1b[E * HID * D];
__device__ __nv_bfloat16 g_w3b[E * HID * D];
__device__ __nv_bfloat16 g_w2b[E * D * HID];
__device__ int   g_cnt[E];
__device__ int   g_cnt2[E];
__device__ int   g_topk_idx[NTOK * 2];
__device__ float g_topk_w[NTOK * 2];
__device__ int   g_perm[MAXSLOTS];
__device__ float g_wgt[MAXSLOTS];

// ------------------------- mma / async helpers --------------------------------------
__device__ __forceinline__ uint32_t f2tf32(float x) {
    uint32_t r;
    asm("cvt.rna.tf32.f32 %0, %1;" : "=r"(r) : "f"(x));
    return r;
}
__device__ __forceinline__ void mma_tf32(float c[4], uint32_t a0, uint32_t a1,
                                         uint32_t a2, uint32_t a3,
                                         uint32_t b0, uint32_t b1) {
    asm volatile(
        "mma.sync.aligned.m16n8k8.row.col.f32.tf32.tf32.f32 "
        "{%0,%1,%2,%3}, {%4,%5,%6,%7}, {%8,%9}, {%0,%1,%2,%3};"
        : "+f"(c[0]), "+f"(c[1]), "+f"(c[2]), "+f"(c[3])
        : "r"(a0), "r"(a1), "r"(a2), "r"(a3), "r"(b0), "r"(b1));
}
__device__ __forceinline__ void ldm_x4(uint32_t* r, uint32_t addr) {
    asm volatile("ldmatrix.sync.aligned.m8n8.x4.shared.b16 {%0,%1,%2,%3}, [%4];"
                 : "=r"(r[0]), "=r"(r[1]), "=r"(r[2]), "=r"(r[3]) : "r"(addr));
}
__device__ __forceinline__ void mma_bf16(float c[4], const uint32_t a[4],
                                         uint32_t b0, uint32_t b1) {
    asm volatile(
        "mma.sync.aligned.m16n8k16.row.col.f32.bf16.bf16.f32 "
        "{%0,%1,%2,%3}, {%4,%5,%6,%7}, {%8,%9}, {%0,%1,%2,%3};"
        : "+f"(c[0]), "+f"(c[1]), "+f"(c[2]), "+f"(c[3])
        : "r"(a[0]), "r"(a[1]), "r"(a[2]), "r"(a[3]), "r"(b0), "r"(b1));
}
__device__ __forceinline__ void cpa16(uint32_t dst, const void* src) {
    asm volatile("cp.async.cg.shared.global [%0], [%1], 16;" :: "r"(dst), "l"(src));
}
__device__ __forceinline__ void cp_commit() {
    asm volatile("cp.async.commit_group;");
}
__device__ __forceinline__ void cp_wait1() {
    asm volatile("cp.async.wait_group 1;");
}
__device__ __forceinline__ int expert_base(int e) {
    int off = 0;
    for (int q = 0; q < e; q++) off += (g_cnt[q] + 127) & ~127;
    return off;
}

// ---------------- prep: init counters/pads + fp32->bf16 weight convert ---------------
__global__ void k_prep(const float* __restrict__ w1, const float* __restrict__ w3,
                       const float* __restrict__ w2) {
    int t = blockIdx.x * 256 + threadIdx.x;
    if (t < MAXSLOTS) { g_wgt[t] = 0.f; g_perm[t] = 0; }
    if (t < E) { g_cnt[t] = 0; g_cnt2[t] = 0; }
    if (t < Bsz * D * S) g_h[t] = 0.f;
    int i = t * 4;
    constexpr int WN = E * HID * D;
    if (i < WN) {
        float4 v1 = *(const float4*)(w1 + i);
        float4 v3 = *(const float4*)(w3 + i);
        float4 v2 = *(const float4*)(w2 + i);
        *(__nv_bfloat162*)(g_w1b + i)     = __float22bfloat162_rn(make_float2(v1.x, v1.y));
        *(__nv_bfloat162*)(g_w1b + i + 2) = __float22bfloat162_rn(make_float2(v1.z, v1.w));
        *(__nv_bfloat162*)(g_w3b + i)     = __float22bfloat162_rn(make_float2(v3.x, v3.y));
        *(__nv_bfloat162*)(g_w3b + i + 2) = __float22bfloat162_rn(make_float2(v3.z, v3.w));
        *(__nv_bfloat162*)(g_w2b + i)     = __float22bfloat162_rn(make_float2(v2.x, v2.y));
        *(__nv_bfloat162*)(g_w2b + i + 2) = __float22bfloat162_rn(make_float2(v2.z, v2.w));
    }
}

// ------------------------- depthwise 3x3 (+optional BN, +optional residual) ----------
__global__ void k_dwconv(const float* __restrict__ in, const float* __restrict__ w9,
                         const float* __restrict__ g, const float* __restrict__ bb,
                         const float* __restrict__ m, const float* __restrict__ v,
                         float* __restrict__ out, int C, int residual) {
    __shared__ float s[34 * 34];
    int b = blockIdx.x / C, c = blockIdx.x % C;
    const float* ip = in + (size_t)(b * C + c) * L;
    int tid = threadIdx.x;
    for (int idx = tid; idx < 34 * 34; idx += 256) {
        int r = idx / 34 - 1, cc = idx % 34 - 1;
        s[idx] = (r >= 0 && r < 32 && cc >= 0 && cc < 32) ? ip[r * 32 + cc] : 0.f;
    }
    __syncthreads();
    float w[9];
#pragma unroll
    for (int i = 0; i < 9; i++) w[i] = w9[c * 9 + i];
    float sc = 1.f, sh = 0.f;
    if (g) { sc = g[c] * rsqrtf(v[c] + EPSV); sh = bb[c] - m[c] * sc; }
    float* op = out + (size_t)(b * C + c) * L;
    for (int idx = tid; idx < 1024; idx += 256) {
        int r = idx >> 5, cc = idx & 31;
        float acc = 0.f;
#pragma unroll
        for (int kr = 0; kr < 3; kr++)
#pragma unroll
            for (int kc = 0; kc < 3; kc++)
                acc += w[kr * 3 + kc] * s[(r + kr) * 34 + cc + kc];
        float val = sc * acc + sh;
        if (residual) val += s[(r + 1) * 34 + cc + 1];
        op[idx] = val;
    }
}

// ------------------------- LN stats only (mu, rsqrt(var)) ---------------------------
__global__ void k_lnstats() {
    int gi = blockIdx.x * 256 + threadIdx.x;
    int b = gi >> 10, l = gi & 1023;
    const float* p = g_x1 + (size_t)b * D * L + l;
    float sum = 0.f, sq = 0.f;
    for (int d = 0; d < D; d++) { float x = p[(size_t)d * L]; sum += x; sq += x * x; }
    float mu = sum * (1.f / D);
    float var = sq * (1.f / D) - mu * mu;
    g_mu[gi] = mu;
    g_rs[gi] = rsqrtf(var + EPSV);
}

// --------- bcdt = bcdt_w @ LN(x1)  (tf32 mma, LN fused, conflict-free Bs) ------------
__global__ __launch_bounds__(256) void k_gemm_bcdt(const float* __restrict__ Wm,
                                                   const float* __restrict__ lnw,
                                                   const float* __restrict__ lnb) {
    __shared__ uint32_t As[64][20];
    __shared__ uint32_t Bs[16][136];
    int b = blockIdx.x, m0 = blockIdx.y * 64, n0 = blockIdx.z * 128;
    int tid = threadIdx.x, lane = tid & 31, wid = tid >> 5;
    int wm = (wid & 1) * 32, wn = (wid >> 1) * 32;
    int g = lane >> 2, tg = lane & 3;
    const float* Bp = g_x1 + (size_t)b * D * L;

    int mA = tid >> 2, kqA = tid & 3;
    int nB = (tid & 31) * 4, kB = tid >> 5;

    float4 mu4 = *(const float4*)&g_mu[b * L + n0 + nB];
    float4 rs4 = *(const float4*)&g_rs[b * L + n0 + nB];

    float acc[2][4][4] = {};
    float4 ra, rb0, rb1;
    ra  = *(const float4*)&Wm[(size_t)(m0 + mA) * 384 + kqA * 4];
    rb0 = *(const float4*)&Bp[(size_t)kB * L + n0 + nB];
    rb1 = *(const float4*)&Bp[(size_t)(kB + 8) * L + n0 + nB];

    for (int it = 0; it < 24; it++) {
        int d0 = it * 16 + kB;
        float w0 = lnw[d0],     c0 = lnb[d0];
        float w1 = lnw[d0 + 8], c1 = lnb[d0 + 8];
        *(uint4*)&As[mA][kqA * 4] =
            make_uint4(f2tf32(ra.x), f2tf32(ra.y), f2tf32(ra.z), f2tf32(ra.w));
        *(uint4*)&Bs[kB][nB] = make_uint4(
            f2tf32((rb0.x - mu4.x) * rs4.x * w0 + c0),
            f2tf32((rb0.y - mu4.y) * rs4.y * w0 + c0),
            f2tf32((rb0.z - mu4.z) * rs4.z * w0 + c0),
            f2tf32((rb0.w - mu4.w) * rs4.w * w0 + c0));
        *(uint4*)&Bs[kB + 8][nB] = make_uint4(
            f2tf32((rb1.x - mu4.x) * rs4.x * w1 + c1),
            f2tf32((rb1.y - mu4.y) * rs4.y * w1 + c1),
            f2tf32((rb1.z - mu4.z) * rs4.z * w1 + c1),
            f2tf32((rb1.w - mu4.w) * rs4.w * w1 + c1));
        __syncthreads();
        if (it + 1 < 24) {
            int k0 = (it + 1) * 16;
            ra  = *(const float4*)&Wm[(size_t)(m0 + mA) * 384 + k0 + kqA * 4];
            rb0 = *(const float4*)&Bp[(size_t)(k0 + kB) * L + n0 + nB];
            rb1 = *(const float4*)&Bp[(size_t)(k0 + kB + 8) * L + n0 + nB];
        }
#pragma unroll
        for (int ks = 0; ks < 16; ks += 8) {
            uint32_t af[2][4], bf[4][2];
#pragma unroll
            for (int mt = 0; mt < 2; mt++) {
                int r = wm + mt * 16 + g;
                af[mt][0] = As[r][ks + tg];     af[mt][1] = As[r + 8][ks + tg];
                af[mt][2] = As[r][ks + 4 + tg]; af[mt][3] = As[r + 8][ks + 4 + tg];
            }
#pragma unroll
            for (int nt = 0; nt < 4; nt++) {
                int c = wn + nt * 8 + g;
                bf[nt][0] = Bs[ks + tg][c]; bf[nt][1] = Bs[ks + 4 + tg][c];
            }
#pragma unroll
            for (int mt = 0; mt < 2; mt++)
#pragma unroll
                for (int nt = 0; nt < 4; nt++)
                    mma_tf32(acc[mt][nt], af[mt][0], af[mt][1], af[mt][2], af[mt][3],
                             bf[nt][0], bf[nt][1]);
        }
        __syncthreads();
    }
    float* Cp = g_bcdt + (size_t)b * C3 * L;
#pragma unroll
    for (int mt = 0; mt < 2; mt++)
#pragma unroll
        for (int h = 0; h < 2; h++) {
            int row = m0 + wm + mt * 16 + g + h * 8;
#pragma unroll
            for (int nt = 0; nt < 4; nt++) {
                int col = n0 + wn + nt * 8 + tg * 2;
                Cp[(size_t)row * L + col]     = acc[mt][nt][h * 2];
                Cp[(size_t)row * L + col + 1] = acc[mt][nt][h * 2 + 1];
            }
        }
}

// ------- fused dws-conv (Bm, Cm, dt) + softmax over L + ab = softmax(dt)*Bm ----------
__global__ __launch_bounds__(256) void k_dwsmax(const float* __restrict__ dws_w) {
    __shared__ float sB[34 * 34], sC[34 * 34], sD[34 * 34];
    __shared__ float red[256];
    int b = blockIdx.x, s = blockIdx.y;
    int tid = threadIdx.x;
    const float* ipB = g_bcdt + ((size_t)b * C3 + s) * L;
    const float* ipC = g_bcdt + ((size_t)b * C3 + S + s) * L;
    const float* ipD = g_bcdt + ((size_t)b * C3 + 2 * S + s) * L;
    for (int idx = tid; idx < 34 * 34; idx += 256) {
        int r = idx / 34 - 1, cc = idx % 34 - 1;
        bool in = (r >= 0 && r < 32 && cc >= 0 && cc < 32);
        int o = r * 32 + cc;
        sB[idx] = in ? ipB[o] : 0.f;
        sC[idx] = in ? ipC[o] : 0.f;
        sD[idx] = in ? ipD[o] : 0.f;
    }
    __syncthreads();
    float wB[9], wC[9], wD[9];
#pragma unroll
    for (int i = 0; i < 9; i++) {
        wB[i] = dws_w[s * 9 + i];
        wC[i] = dws_w[(S + s) * 9 + i];
        wD[i] = dws_w[(2 * S + s) * 9 + i];
    }
    float bm[4], dt[4];
    float* Cp = g_bcdt2 + ((size_t)b * C3 + S + s) * L;
    float mx = -1e30f;
#pragma unroll
    for (int i = 0; i < 4; i++) {
        int idx = tid + i * 256;
        int r = idx >> 5, cc = idx & 31;
        float aB = 0.f, aC = 0.f, aD = 0.f;
#pragma unroll
        for (int kr = 0; kr < 3; kr++)
#pragma unroll
            for (int kc = 0; kc < 3; kc++) {
                float vB = sB[(r + kr) * 34 + cc + kc];
                float vC = sC[(r + kr) * 34 + cc + kc];
                float vD = sD[(r + kr) * 34 + cc + kc];
                aB += wB[kr * 3 + kc] * vB;
                aC += wC[kr * 3 + kc] * vC;
                aD += wD[kr * 3 + kc] * vD;
            }
        bm[i] = aB; dt[i] = aD;
        Cp[idx] = aC;
        mx = fmaxf(mx, aD);
    }
    red[tid] = mx; __syncthreads();
    for (int o = 128; o > 0; o >>= 1) { if (tid < o) red[tid] = fmaxf(red[tid], red[tid + o]); __syncthreads(); }
    mx = red[0]; __syncthreads();
    float e[4]; float sum = 0.f;
#pragma unroll
    for (int i = 0; i < 4; i++) { e[i] = __expf(dt[i] - mx); sum += e[i]; }
    red[tid] = sum; __syncthreads();
    for (int o = 128; o > 0; o >>= 1) { if (tid < o) red[tid] += red[tid + o]; __syncthreads(); }
    float inv = 1.f / red[0];
    float* ab = g_ab + ((size_t)b * S + s) * L;
#pragma unroll
    for (int i = 0; i < 4; i++) ab[tid + i * 256] = e[i] * inv * bm[i];
}

// --- h[b,d,s] = sum_l LN(x1)*ab  (tf32 mma, LN fused, split-K=8) ---------------------
__global__ __launch_bounds__(256) void k_gemm_h(const float* __restrict__ lnw,
                                                const float* __restrict__ lnb) {
    __shared__ uint32_t As[128][20];
    __shared__ uint32_t Bs[64][20];
    __shared__ float smu[128], srs[128];
    int b = blockIdx.x, m0 = blockIdx.y * 128, kc = blockIdx.z;
    int tid = threadIdx.x, lane = tid & 31, wid = tid >> 5;
    int wm = (wid & 3) * 32, wn = (wid >> 2) * 32;
    int g = lane >> 2, tg = lane & 3;
    const float* Ap = g_x1 + (size_t)b * D * L;
    const float* Bp = g_ab + (size_t)b * S * L;

    int mA = tid >> 1, lhA = tid & 1;
    int nB = tid >> 2, kqB = tid & 3;
    int kbase = kc * 128;

    if (tid < 128) {
        smu[tid] = g_mu[b * L + kbase + tid];
        srs[tid] = g_rs[b * L + kbase + tid];
    }
    float wA = lnw[m0 + mA], cA = lnb[m0 + mA];
    __syncthreads();

    float acc[2][4][4] = {};
    float4 ra0, ra1, rb;
    ra0 = *(const float4*)&Ap[(size_t)(m0 + mA) * L + kbase + lhA * 8];
    ra1 = *(const float4*)&Ap[(size_t)(m0 + mA) * L + kbase + lhA * 8 + 4];
    rb  = *(const float4*)&Bp[(size_t)nB * L + kbase + kqB * 4];

    for (int it = 0; it < 8; it++) {
        int lx = it * 16 + lhA * 8;
        *(uint4*)&As[mA][lhA * 8] = make_uint4(
            f2tf32((ra0.x - smu[lx + 0]) * srs[lx + 0] * wA + cA),
            f2tf32((ra0.y - smu[lx + 1]) * srs[lx + 1] * wA + cA),
            f2tf32((ra0.z - smu[lx + 2]) * srs[lx + 2] * wA + cA),
            f2tf32((ra0.w - smu[lx + 3]) * srs[lx + 3] * wA + cA));
        *(uint4*)&As[mA][lhA * 8 + 4] = make_uint4(
            f2tf32((ra1.x - smu[lx + 4]) * srs[lx + 4] * wA + cA),
            f2tf32((ra1.y - smu[lx + 5]) * srs[lx + 5] * wA + cA),
            f2tf32((ra1.z - smu[lx + 6]) * srs[lx + 6] * wA + cA),
            f2tf32((ra1.w - smu[lx + 7]) * srs[lx + 7] * wA + cA));
        Bs[nB][kqB * 4 + 0] = f2tf32(rb.x); Bs[nB][kqB * 4 + 1] = f2tf32(rb.y);
        Bs[nB][kqB * 4 + 2] = f2tf32(rb.z); Bs[nB][kqB * 4 + 3] = f2tf32(rb.w);
        __syncthreads();
        if (it + 1 < 8) {
            int k0 = kbase + (it + 1) * 16;
            ra0 = *(const float4*)&Ap[(size_t)(m0 + mA) * L + k0 + lhA * 8];
            ra1 = *(const float4*)&Ap[(size_t)(m0 + mA) * L + k0 + lhA * 8 + 4];
            rb  = *(const float4*)&Bp[(size_t)nB * L + k0 + kqB * 4];
        }
#pragma unroll
        for (int ks = 0; ks < 16; ks += 8) {
            uint32_t af[2][4], bf[4][2];
#pragma unroll
            for (int mt = 0; mt < 2; mt++) {
                int r = wm + mt * 16 + g;
                af[mt][0] = As[r][ks + tg];     af[mt][1] = As[r + 8][ks + tg];
                af[mt][2] = As[r][ks + 4 + tg]; af[mt][3] = As[r + 8][ks + 4 + tg];
            }
#pragma unroll
            for (int nt = 0; nt < 4; nt++) {
                int c = wn + nt * 8 + g;
                bf[nt][0] = Bs[c][ks + tg]; bf[nt][1] = Bs[c][ks + 4 + tg];
            }
#pragma unroll
            for (int mt = 0; mt < 2; mt++)
#pragma unroll
                for (int nt = 0; nt < 4; nt++)
                    mma_tf32(acc[mt][nt], af[mt][0], af[mt][1], af[mt][2], af[mt][3],
                             bf[nt][0], bf[nt][1]);
        }
        __syncthreads();
    }
    float* Cp = g_h + (size_t)b * D * S;
#pragma unroll
    for (int mt = 0; mt < 2; mt++)
#pragma unroll
        for (int h = 0; h < 2; h++) {
            int row = m0 + wm + mt * 16 + g + h * 8;
#pragma unroll
            for (int nt = 0; nt < 4; nt++) {
                int col = wn + nt * 8 + tg * 2;
                atomicAdd(&Cp[(size_t)row * S + col],     acc[mt][nt][h * 2]);
                atomicAdd(&Cp[(size_t)row * S + col + 1], acc[mt][nt][h * 2 + 1]);
            }
        }
}

// ------------- h2 = silu(hproj @ h) -> out_h  (tf32 mma, 64x64 tiles, K=384) ---------
__global__ __launch_bounds__(256) void k_hproj(const float* __restrict__ Wp,
                                               float* __restrict__ outh) {
    __shared__ uint32_t As[64][20];
    __shared__ uint32_t Bs[64][20];
    int b = blockIdx.x, m0 = blockIdx.y * 64;
    int tid = threadIdx.x, lane = tid & 31, wid = tid >> 5;
    int wm = (wid & 1) * 32, wn = (wid >> 1) * 16;
    int g = lane >> 2, tg = lane & 3;
    const float* Bp = g_h + (size_t)b * D * S;

    int mA = tid >> 2, kqA = tid & 3;
    int nB = tid & 63, kqB = tid >> 6;

    float acc[2][2][4] = {};
    float4 ra;
    float rb[4];
    ra = *(const float4*)&Wp[(size_t)(m0 + mA) * 384 + kqA * 4];
#pragma unroll
    for (int j = 0; j < 4; j++) rb[j] = Bp[(size_t)(kqB * 4 + j) * S + nB];

    for (int it = 0; it < 24; it++) {
        *(uint4*)&As[mA][kqA * 4] =
            make_uint4(f2tf32(ra.x), f2tf32(ra.y), f2tf32(ra.z), f2tf32(ra.w));
#pragma unroll
        for (int j = 0; j < 4; j++) Bs[nB][kqB * 4 + j] = f2tf32(rb[j]);
        __syncthreads();
        if (it + 1 < 24) {
            int k0 = (it + 1) * 16;
            ra = *(const float4*)&Wp[(size_t)(m0 + mA) * 384 + k0 + kqA * 4];
#pragma unroll
            for (int j = 0; j < 4; j++) rb[j] = Bp[(size_t)(k0 + kqB * 4 + j) * S + nB];
        }
#pragma unroll
        for (int ks = 0; ks < 16; ks += 8) {
            uint32_t af[2][4], bf[2][2];
#pragma unroll
            for (int mt = 0; mt < 2; mt++) {
                int r = wm + mt * 16 + g;
                af[mt][0] = As[r][ks + tg];     af[mt][1] = As[r + 8][ks + tg];
                af[mt][2] = As[r][ks + 4 + tg]; af[mt][3] = As[r + 8][ks + 4 + tg];
            }
#pragma unroll
            for (int nt = 0; nt < 2; nt++) {
                int c = wn + nt * 8 + g;
                bf[nt][0] = Bs[c][ks + tg]; bf[nt][1] = Bs[c][ks + 4 + tg];
            }
#pragma unroll
            for (int mt = 0; mt < 2; mt++)
#pragma unroll
                for (int nt = 0; nt < 2; nt++)
                    mma_tf32(acc[mt][nt], af[mt][0], af[mt][1], af[mt][2], af[mt][3],
                             bf[nt][0], bf[nt][1]);
        }
        __syncthreads();
    }
    float* Cp = outh + (size_t)b * D * S;
#pragma unroll
    for (int mt = 0; mt < 2; mt++)
#pragma unroll
        for (int h = 0; h < 2; h++) {
            int row = m0 + wm + mt * 16 + g + h * 8;
#pragma unroll
            for (int nt = 0; nt < 2; nt++) {
                int col = wn + nt * 8 + tg * 2;
                float xa = acc[mt][nt][h * 2];
                float xb = acc[mt][nt][h * 2 + 1];
                Cp[(size_t)row * S + col]     = xa / (1.f + __expf(-xa));
                Cp[(size_t)row * S + col + 1] = xb / (1.f + __expf(-xb));
            }
        }
}

// ------------- x2 = x1 + h2 @ Cm  (tf32 mma, conflict-free Bs, K=64) -----------------
__global__ __launch_bounds__(256) void k_gemm_y(const float* __restrict__ outh) {
    __shared__ uint32_t As[128][20];
    __shared__ uint32_t Bs[16][136];
    int b = blockIdx.x, m0 = blockIdx.y * 128, n0 = blockIdx.z * 128;
    int tid = threadIdx.x, lane = tid & 31, wid = tid >> 5;
    int wm = (wid & 1) * 64, wn = (wid >> 1) * 32;
    int g = lane >> 2, tg = lane & 3;
    const float* Ap = outh + (size_t)b * D * S;
    const float* Bp = g_bcdt2 + ((size_t)b * C3 + S) * L;

    int mA = tid >> 1, lhA = tid & 1;
    int nB = (tid & 31) * 4, kB = tid >> 5;

    float acc[4][4][4] = {};
    float4 ra0, ra1, rb0, rb1;
    ra0 = *(const float4*)&Ap[(size_t)(m0 + mA) * S + lhA * 8];
    ra1 = *(const float4*)&Ap[(size_t)(m0 + mA) * S + lhA * 8 + 4];
    rb0 = *(const float4*)&Bp[(size_t)kB * L + n0 + nB];
    rb1 = *(const float4*)&Bp[(size_t)(kB + 8) * L + n0 + nB];

    for (int it = 0; it < 4; it++) {
        *(uint4*)&As[mA][lhA * 8] =
            make_uint4(f2tf32(ra0.x), f2tf32(ra0.y), f2tf32(ra0.z), f2tf32(ra0.w));
        *(uint4*)&As[mA][lhA * 8 + 4] =
            make_uint4(f2tf32(ra1.x), f2tf32(ra1.y), f2tf32(ra1.z), f2tf32(ra1.w));
        *(uint4*)&Bs[kB][nB] =
            make_uint4(f2tf32(rb0.x), f2tf32(rb0.y), f2tf32(rb0.z), f2tf32(rb0.w));
        *(uint4*)&Bs[kB + 8][nB] =
            make_uint4(f2tf32(rb1.x), f2tf32(rb1.y), f2tf32(rb1.z), f2tf32(rb1.w));
        __syncthreads();
        if (it + 1 < 4) {
            int k0 = (it + 1) * 16;
            ra0 = *(const float4*)&Ap[(size_t)(m0 + mA) * S + k0 + lhA * 8];
            ra1 = *(const float4*)&Ap[(size_t)(m0 + mA) * S + k0 + lhA * 8 + 4];
            rb0 = *(const float4*)&Bp[(size_t)(k0 + kB) * L + n0 + nB];
            rb1 = *(const float4*)&Bp[(size_t)(k0 + kB + 8) * L + n0 + nB];
        }
#pragma unroll
        for (int ks = 0; ks < 16; ks += 8) {
            uint32_t af[4][4], bf[4][2];
#pragma unroll
            for (int mt = 0; mt < 4; mt++) {
                int r = wm + mt * 16 + g;
                af[mt][0] = As[r][ks + tg];     af[mt][1] = As[r + 8][ks + tg];
                af[mt][2] = As[r][ks + 4 + tg]; af[mt][3] = As[r + 8][ks + 4 + tg];
            }
#pragma unroll
            for (int nt = 0; nt < 4; nt++) {
                int c = wn + nt * 8 + g;
                bf[nt][0] = Bs[ks + tg][c]; bf[nt][1] = Bs[ks + 4 + tg][c];
            }
#pragma unroll
            for (int mt = 0; mt < 4; mt++)
#pragma unroll
                for (int nt = 0; nt < 4; nt++)
                    mma_tf32(acc[mt][nt], af[mt][0], af[mt][1], af[mt][2], af[mt][3],
                             bf[nt][0], bf[nt][1]);
        }
        __syncthreads();
    }
#pragma unroll
    for (int mt = 0; mt < 4; mt++)
#pragma unroll
        for (int h = 0; h < 2; h++) {
            int row = m0 + wm + mt * 16 + g + h * 8;
#pragma unroll
            for (int nt = 0; nt < 4; nt++) {
                int col = n0 + wn + nt * 8 + tg * 2;
                size_t o = (size_t)b * D * L + (size_t)row * L + col;
                g_x2[o]     = g_x1[o]     + acc[mt][nt][h * 2];
                g_x2[o + 1] = g_x1[o + 1] + acc[mt][nt][h * 2 + 1];
            }
        }
}

// ---------- fused: NCHW -> bf16 token transpose + router (logits in fp32) ------------
__global__ __launch_bounds__(256) void k_transroute(
        const float* __restrict__ xin, const float* __restrict__ gw,
        const float* __restrict__ gb) {
    __shared__ float sg[E * 385];
    __shared__ float s[32][33];
    __shared__ float lgb[32][8];
    int b = blockIdx.x, l0 = blockIdx.y * 32;
    int tid = threadIdx.x;
    for (int i = tid; i < E * D; i += 256)
        sg[(i / D) * 385 + (i % D)] = gw[i];

    int rr = tid >> 5, cc = tid & 31;
    int ch = tid & 31, tk = tid >> 5;
    int tok = tid >> 3, ex = tid & 7;
    float lg = 0.f;

    for (int dc = 0; dc < 12; dc++) {
        int d0 = dc * 32;
        __syncthreads();
#pragma unroll
        for (int i = 0; i < 4; i++)
            s[rr + i * 8][cc] = xin[((size_t)b * D + d0 + rr + i * 8) * L + l0 + cc];
        __syncthreads();
#pragma unroll
        for (int j = 0; j < 4; j++) {
            int t2 = tk + j * 8;
            g_xTb[((size_t)b * L + l0 + t2) * D + d0 + ch] =
                __float2bfloat16(s[ch][t2]);
        }
        const float* gp = sg + ex * 385 + d0;
#pragma unroll
        for (int dd = 0; dd < 32; dd++)
            lg += s[dd][tok] * gp[dd];
    }
    lgb[tok][ex] = lg;
    __syncthreads();
    if (tid < 32) {
        int n = b * L + l0 + tid;
        float v[E];
#pragma unroll
        for (int e = 0; e < E; e++) v[e] = lgb[tid][e] + gb[e];
        int i0 = 0; float v0 = v[0];
#pragma unroll
        for (int e = 1; e < E; e++) if (v[e] > v0) { v0 = v[e]; i0 = e; }
        int i1 = -1; float v1 = -1e30f;
#pragma unroll
        for (int e = 0; e < E; e++) if (e != i0 && v[e] > v1) { v1 = v[e]; i1 = e; }
        float p0 = 1.f / (1.f + __expf(v1 - v0));
        g_topk_idx[n * 2] = i0; g_topk_idx[n * 2 + 1] = i1;
        g_topk_w[n * 2] = p0;   g_topk_w[n * 2 + 1] = 1.f - p0;
        atomicAdd(&g_cnt[i0], 1); atomicAdd(&g_cnt[i1], 1);
    }
}

// ---------------- scatter (offsets computed inline from g_cnt) -----------------------
__global__ void k_scatter() {
    __shared__ int soff[E];
    if (threadIdx.x < E) soff[threadIdx.x] = expert_base(threadIdx.x);
    __syncthreads();
    int n = blockIdx.x * 256 + threadIdx.x;
#pragma unroll
    for (int k = 0; k < 2; k++) {
        int e = g_topk_idx[n * 2 + k];
        int pos = soff[e] + atomicAdd(&g_cnt2[e], 1);
        g_perm[pos] = n;
        g_wgt[pos] = g_topk_w[n * 2 + k];
    }
}

// ------------------- MoE GEMM1 (bf16 mma + cp.async 3-stage, k-tile 64) --------------
constexpr int MT_BYTES = 18432;       // 128 rows * 144B
constexpr int MOE1_SMEM = 166400;
constexpr int MOE2_SMEM = 110592;

__global__ __launch_bounds__(256) void k_moe1(
        const float* __restrict__ B1, const float* __restrict__ B3) {
    extern __shared__ char sm[];
    int* sperm = (int*)(sm + 165888);

    int e = blockIdx.x;
    int cnt = g_cnt[e];
    int m0 = blockIdx.y * 128;
    if (m0 >= cnt) return;
    int base = expert_base(e);
    int n0 = blockIdx.z * 128;

    int tid = threadIdx.x, lane = tid & 31, wid = tid >> 5;
    int wm = (wid & 1) * 64, wn = (wid >> 1) * 32;
    int g = lane >> 2, tg = lane & 3;

    if (tid < 128) sperm[tid] = g_perm[base + m0 + tid];
    __syncthreads();

    uint32_t smBase = (uint32_t)__cvta_generic_to_shared(sm);
    uint32_t aFrag = (wm + (lane & 15)) * 144 + (lane >> 4) * 16;
    uint32_t bFrag = (wn + (lane >> 4) * 8 + (lane & 7)) * 144 + ((lane >> 3) & 1) * 16;

    constexpr int KT = D / 64;   // 6
    auto issue = [&](int t) {
        if (t < KT) {
            int k0 = t * 64;
            uint32_t off = (uint32_t)(t % 3) * MT_BYTES;
#pragma unroll
            for (int j = 0; j < 4; j++) {
                int li = tid + j * 256;
                int row = li >> 3, lc = li & 7;
                uint32_t so = off + row * 144 + lc * 16;
                cpa16(smBase + so, g_xTb + (size_t)sperm[row] * D + k0 + lc * 8);
                size_t wgo = ((size_t)e * HID + n0 + row) * D + k0 + lc * 8;
                cpa16(smBase + 55296 + so,  g_w1b + wgo);
                cpa16(smBase + 110592 + so, g_w3b + wgo);
            }
        }
        cp_commit();
    };

    float acc1[4][4][4] = {}, acc3[4][4][4] = {};
    issue(0); issue(1);

    for (int it = 0; it < KT; it++) {
        cp_wait1();
        __syncthreads();
        issue(it + 2);
        uint32_t st = (uint32_t)(it % 3) * MT_BYTES;
#pragma unroll
        for (int ks = 0; ks < 4; ks++) {
            uint32_t af[4][4], bf1[2][4], bf3[2][4];
#pragma unroll
            for (int mt = 0; mt < 4; mt++)
                ldm_x4(af[mt], smBase + st + aFrag + mt * 2304 + ks * 32);
#pragma unroll
            for (int np = 0; np < 2; np++) {
                ldm_x4(bf1[np], smBase + 55296 + st + bFrag + np * 2304 + ks * 32);
                ldm_x4(bf3[np], smBase + 110592 + st + bFrag + np * 2304 + ks * 32);
            }
#pragma unroll
            for (int mt = 0; mt < 4; mt++)
#pragma unroll
                for (int nt = 0; nt < 4; nt++) {
                    int np = nt >> 1, hf = (nt & 1) * 2;
                    mma_bf16(acc1[mt][nt], af[mt], bf1[np][hf], bf1[np][hf + 1]);
                    mma_bf16(acc3[mt][nt], af[mt], bf3[np][hf], bf3[np][hf + 1]);
                }
        }
    }

#pragma unroll
    for (int mt = 0; mt < 4; mt++) {
#pragma unroll
        for (int nt = 0; nt < 4; nt++) {
            int cl = n0 + wn + nt * 8 + tg * 2;
            float bb1a = B1[e * HID + cl], bb1b = B1[e * HID + cl + 1];
            float bb3a = B3[e * HID + cl], bb3b = B3[e * HID + cl + 1];
#pragma unroll
            for (int h = 0; h < 2; h++) {
                int rl = wm + mt * 16 + g + h * 8;
                float x1a = acc1[mt][nt][h * 2] + bb1a;
                float x1b = acc1[mt][nt][h * 2 + 1] + bb1b;
                float x3a = acc3[mt][nt][h * 2] + bb3a;
                float x3b = acc3[mt][nt][h * 2 + 1] + bb3b;
                float oa = (x1a / (1.f + __expf(-x1a))) * x3a;
                float ob = (x1b / (1.f + __expf(-x1b))) * x3b;
                *(__nv_bfloat162*)&g_heb[(size_t)(base + m0 + rl) * HID + cl] =
                    __float22bfloat162_rn(make_float2(oa, ob));
            }
        }
    }
}

// ------------------- MoE GEMM2 (bf16 mma + cp.async 3-stage, k-tile 64) --------------
__global__ __launch_bounds__(256) void k_moe2(
        const float* __restrict__ b2v, float* __restrict__ outx) {
    extern __shared__ char sm[];

    int e = blockIdx.x;
    int cnt = g_cnt[e];
    int m0 = blockIdx.y * 128;
    if (m0 >= cnt) return;
    int base = expert_base(e);
    int n0 = blockIdx.z * 128;

    int tid = threadIdx.x, lane = tid & 31, wid = tid >> 5;
    int wm = (wid & 1) * 64, wn = (wid >> 1) * 32;
    int g = lane >> 2, tg = lane & 3;

    uint32_t smBase = (uint32_t)__cvta_generic_to_shared(sm);
    uint32_t aFrag = (wm + (lane & 15)) * 144 + (lane >> 4) * 16;
    uint32_t bFrag = (wn + (lane >> 4) * 8 + (lane & 7)) * 144 + ((lane >> 3) & 1) * 16;

    constexpr int KT = HID / 64;  // 12
    auto issue = [&](int t) {
        if (t < KT) {
            int k0 = t * 64;
            uint32_t off = (uint32_t)(t % 3) * MT_BYTES;
#pragma unroll
            for (int j = 0; j < 4; j++) {
                int li = tid + j * 256;
                int row = li >> 3, lc = li & 7;
                uint32_t so = off + row * 144 + lc * 16;
                cpa16(smBase + so,
                      g_heb + (size_t)(base + m0 + row) * HID + k0 + lc * 8);
                cpa16(smBase + 55296 + so,
                      g_w2b + ((size_t)e * D + n0 + row) * HID + k0 + lc * 8);
            }
        }
        cp_commit();
    };

    float acc[4][4][4] = {};
    issue(0); issue(1);

    for (int it = 0; it < KT; it++) {
        cp_wait1();
        __syncthreads();
        issue(it + 2);
        uint32_t st = (uint32_t)(it % 3) * MT_BYTES;
#pragma unroll
        for (int ks = 0; ks < 4; ks++) {
            uint32_t af[4][4], bf[2][4];
#pragma unroll
            for (int mt = 0; mt < 4; mt++)
                ldm_x4(af[mt], smBase + st + aFrag + mt * 2304 + ks * 32);
#pragma unroll
            for (int np = 0; np < 2; np++)
                ldm_x4(bf[np], smBase + 55296 + st + bFrag + np * 2304 + ks * 32);
#pragma unroll
            for (int mt = 0; mt < 4; mt++)
#pragma unroll
                for (int nt = 0; nt < 4; nt++) {
                    int np = nt >> 1, hf = (nt & 1) * 2;
                    mma_bf16(acc[mt][nt], af[mt], bf[np][hf], bf[np][hf + 1]);
                }
        }
    }

#pragma unroll
    for (int mt = 0; mt < 4; mt++) {
#pragma unroll
        for (int h = 0; h < 2; h++) {
            int rl = wm + mt * 16 + g + h * 8;
            float w = g_wgt[base + m0 + rl];
            if (w == 0.f) continue;
            int n = g_perm[base + m0 + rl];
            int b = n >> 10, l = n & 1023;
#pragma unroll
            for (int nt = 0; nt < 4; nt++) {
                int cl = n0 + wn + nt * 8 + tg * 2;
                float v0 = (acc[mt][nt][h * 2] + b2v[e * D + cl]) * w;
                float v1 = (acc[mt][nt][h * 2 + 1] + b2v[e * D + cl + 1]) * w;
                atomicAdd(&outx[((size_t)b * D + cl) * L + l], v0);
                atomicAdd(&outx[((size_t)b * D + cl + 1) * L + l], v1);
            }
        }
    }
}

// ------------------------- launch ---------------------------------------------------
extern "C" void kernel_launch(void* const* d_in, const int* in_sizes, int n_in,
                              void* d_out, int out_size) {
    const float* x      = (const float*)d_in[0];
    const float* dw1_w  = (const float*)d_in[1];
    const float* bn1_g  = (const float*)d_in[2];
    const float* bn1_b  = (const float*)d_in[3];
    const float* bn1_m  = (const float*)d_in[4];
    const float* bn1_v  = (const float*)d_in[5];
    const float* dw2_w  = (const float*)d_in[6];
    const float* bn2_g  = (const float*)d_in[7];
    const float* bn2_b  = (const float*)d_in[8];
    const float* bn2_m  = (const float*)d_in[9];
    const float* bn2_v  = (const float*)d_in[10];
    const float* ln_w   = (const float*)d_in[11];
    const float* ln_b   = (const float*)d_in[12];
    const float* bcdt_w = (const float*)d_in[13];
    const float* dws_w  = (const float*)d_in[14];
    const float* hproj_w= (const float*)d_in[15];
    // d_in[16] = A (cancels inside softmax over L)
    const float* gate_w = (const float*)d_in[17];
    const float* gate_b = (const float*)d_in[18];
    const float* w1     = (const float*)d_in[19];
    const float* b1     = (const float*)d_in[20];
    const float* w2     = (const float*)d_in[21];
    const float* b2     = (const float*)d_in[22];
    const float* w3     = (const float*)d_in[23];
    const float* b3     = (const float*)d_in[24];

    float* out_x = (float*)d_out;
    float* out_h = out_x + (size_t)Bsz * D * L;

    float* px1;    cudaGetSymbolAddress((void**)&px1, g_x1);
    float* px2;    cudaGetSymbolAddress((void**)&px2, g_x2);

    static bool init_done = false;
    static cudaStream_t s2 = nullptr;
    static cudaEvent_t evFork = nullptr, evJoin = nullptr;
    if (!init_done) {
        cudaFuncSetAttribute(k_moe1, cudaFuncAttributeMaxDynamicSharedMemorySize, MOE1_SMEM);
        cudaFuncSetAttribute(k_moe2, cudaFuncAttributeMaxDynamicSharedMemorySize, MOE2_SMEM);
        if (cudaStreamCreateWithFlags(&s2, cudaStreamNonBlocking) != cudaSuccess) s2 = nullptr;
        if (s2) {
            if (cudaEventCreateWithFlags(&evFork, cudaEventDisableTiming) != cudaSuccess ||
                cudaEventCreateWithFlags(&evJoin, cudaEventDisableTiming) != cudaSuccess) {
                s2 = nullptr;
            }
        }
        init_done = true;
    }

    // prep (init + weight conversion): forked onto s2 when available
    if (s2) {
        cudaEventRecord(evFork, 0);
        cudaStreamWaitEvent(s2, evFork, 0);
        k_prep<<<2304, 256, 0, s2>>>(w1, w3, w2);
        cudaEventRecord(evJoin, s2);
    } else {
        k_prep<<<2304, 256>>>(w1, w3, w2);
    }

    // x1 = x + bn1(dw1(x))
    k_dwconv<<<Bsz * D, 256>>>(x, dw1_w, bn1_g, bn1_b, bn1_m, bn1_v, px1, D, 1);
    // LN stats only (normalization fused into consumers)
    k_lnstats<<<NTOK / 256, 256>>>();
    // bcdt (tf32, LN fused into B-operand load)
    k_gemm_bcdt<<<dim3(Bsz, 3, 8), 256>>>(bcdt_w, ln_w, ln_b);
    // fused dws conv + softmax (Cm -> g_bcdt2, ab -> g_ab)
    k_dwsmax<<<dim3(Bsz, S), 256>>>(dws_w);
    // join prep before g_h atomics (k_gemm_h needs g_h zeroed)
    if (s2) cudaStreamWaitEvent(0, evJoin, 0);
    // h = LN(x1) @ (Am*Bm)^T (tf32, LN fused, split-K=8)
    k_gemm_h<<<dim3(Bsz, 3, 8), 256>>>(ln_w, ln_b);
    // h2 = silu(hproj @ h) -> second output (tf32 mma, 64-row tiles, 96 CTAs)
    k_hproj<<<dim3(Bsz, 6), 256>>>(hproj_w, out_h);
    // x2 = x1 + h2 @ Cm (tf32)
    k_gemm_y<<<dim3(Bsz, 3, 8), 256>>>(out_h);
    // x3 = x2 + bn2(dw2(x2)) -> first output (MoE adds on top)
    k_dwconv<<<Bsz * D, 256>>>(px2, dw2_w, bn2_g, bn2_b, bn2_m, bn2_v, out_x, D, 1);
    // fused bf16 transpose + router
    k_transroute<<<dim3(Bsz, 32), 256>>>(out_x, gate_w, gate_b);
    // scatter (expert offsets computed inline)
    k_scatter<<<NTOK / 256, 256>>>();
    // MoE (bf16 mma.sync, 256 threads, cp.async 3-stage, k-tile 64)
    k_moe1<<<dim3(E, 128, 6), 256, MOE1_SMEM>>>(b1, b3);
    k_moe2<<<dim3(E, 128, 3), 256, MOE2_SMEM>>>(b2, out_x);
}